// round 7
// baseline (speedup 1.0000x reference)
#include <cuda_runtime.h>
#include <cuda_bf16.h>
#include <cstdint>

#define BB 8
#define NN 256
#define DD 128
#define HH 8
#define DH 64
#define DQ 32
#define MAXD 5.0f

// ---------------- device scratch (no allocation allowed) ----------------
__device__ float         g_nproj[BB * NN * DH];   // [B,N,64] fp32
__device__ __nv_bfloat16 g_Wb1[DH * DH];          // folded layer-1 weight [o][k] bf16
__device__ __nv_bfloat16 g_Wb2[DQ * DH];          // W2 [m][o] bf16
__device__ float         g_b1eff[DH];
__device__ float         g_w1c[DH];               // W1[:,96]/MAXD

// ---------------- helpers ----------------
__device__ __forceinline__ uint32_t smem_u32(const void* p) {
    uint32_t a;
    asm("{ .reg .u64 t; cvta.to.shared.u64 t, %1; cvt.u32.u64 %0, t; }" : "=r"(a) : "l"(p));
    return a;
}
#define SWZ128(off) ((off) ^ (((off) >> 3) & 0x70))

// pack -> bf16x2 {lo=a, hi=b}
#define PACK_BF16X2(res, a, b) \
    asm("cvt.rn.satfinite.bf16x2.f32 %0, %1, %2;" : "=r"(res) : "f"(b), "f"(a))

#define STS128(a, r0, r1, r2, r3) \
    asm volatile("st.shared.v4.b32 [%0], {%1,%2,%3,%4};" :: "r"(a), "r"(r0), "r"(r1), "r"(r2), "r"(r3) : "memory")

__device__ __forceinline__ void ldsm_x4(uint32_t* r, uint32_t addr) {
    asm volatile("ldmatrix.sync.aligned.m8n8.x4.shared.b16 {%0,%1,%2,%3}, [%4];"
                 : "=r"(r[0]), "=r"(r[1]), "=r"(r[2]), "=r"(r[3]) : "r"(addr));
}
__device__ __forceinline__ void ldsm_x2(uint32_t* r, uint32_t addr) {
    asm volatile("ldmatrix.sync.aligned.m8n8.x2.shared.b16 {%0,%1}, [%2];"
                 : "=r"(r[0]), "=r"(r[1]) : "r"(addr));
}
__device__ __forceinline__ void mma16816(float& d0, float& d1, float& d2, float& d3,
                                         uint32_t a0, uint32_t a1, uint32_t a2, uint32_t a3,
                                         uint32_t b0, uint32_t b1) {
    asm volatile("mma.sync.aligned.m16n8k16.row.col.f32.bf16.bf16.f32 "
                 "{%0,%1,%2,%3}, {%4,%5,%6,%7}, {%8,%9}, {%0,%1,%2,%3};"
                 : "+f"(d0), "+f"(d1), "+f"(d2), "+f"(d3)
                 : "r"(a0), "r"(a1), "r"(a2), "r"(a3), "r"(b0), "r"(b1));
}

// ---------------- SMEM layout (dynamic) ----------------
#define SM_BUF   0        // 256 rows x 128B : ef -> h1 -> h2      (32768)
#define SM_WB1   32768    // 64 x 128B swizzled                    (8192)
#define SM_WB2   40960    // 32 x 128B swizzled                    (4096)
#define SM_CD    45056    // 256 f                                 (1024)
#define SM_NI    46080    // 64 f
#define SM_B1    46336    // 64 f
#define SM_W1C   46592    // 64 f
#define SM_B2    46848    // 32 f
#define SM_B3    46976    // 8 f
#define SM_W3    47008    // 256 f
#define SM_TOTAL 48032

// ---------------------------------------------------------------------------
// merged prep: blocks 0..95 fold weights to bf16; blocks 96.. compute nproj.
// ---------------------------------------------------------------------------
__global__ void prep_kernel(const float* __restrict__ nf,
                            const float* __restrict__ Wn,
                            const float* __restrict__ bn,
                            const float* __restrict__ W_edge,
                            const float* __restrict__ b_edge,
                            const float* __restrict__ W1,
                            const float* __restrict__ b1,
                            const float* __restrict__ W2) {
    const int blk = blockIdx.x;
    const int t = threadIdx.x;   // 64 threads
    if (blk < DH) {                       // Wb1 row o = blk
        int o = blk, k = t;
        float acc = W1[o * 97 + k];
        #pragma unroll
        for (int m = 0; m < DQ; ++m)
            acc = fmaf(W1[o * 97 + 64 + m], W_edge[m * DD + k], acc);
        g_Wb1[o * DH + k] = __float2bfloat16_rn(acc);
        if (k == 0) {
            float bb = b1[o];
            #pragma unroll
            for (int m = 0; m < DQ; ++m)
                bb = fmaf(W1[o * 97 + 64 + m], b_edge[m], bb);
            g_b1eff[o] = bb;
            g_w1c[o] = W1[o * 97 + 96] * (1.0f / MAXD);
        }
    } else if (blk < DH + DQ) {           // Wb2 row m = blk-64
        int m = blk - DH;
        g_Wb2[m * DH + t] = __float2bfloat16_rn(W2[m * DH + t]);
    } else {                              // nproj row
        int row = blk - (DH + DQ);
        __shared__ float sx[DD];
        const float* x = nf + (size_t)row * DD;
        sx[t] = x[t];
        sx[t + 64] = x[t + 64];
        __syncthreads();
        const float* w = Wn + t * DD;
        float a0 = 0.f, a1 = 0.f, a2 = 0.f, a3 = 0.f;
        #pragma unroll
        for (int k = 0; k < DD; k += 4) {
            a0 = fmaf(w[k + 0], sx[k + 0], a0);
            a1 = fmaf(w[k + 1], sx[k + 1], a1);
            a2 = fmaf(w[k + 2], sx[k + 2], a2);
            a3 = fmaf(w[k + 3], sx[k + 3], a3);
        }
        g_nproj[row * DH + t] = (a0 + a1) + (a2 + a3) + bn[t];
    }
}

// ---------------------------------------------------------------------------
// Main: CTA per (b,i). Warp-level mma.sync bf16 for layers 1-2.
// MUFU diet: tanh.approx.bf16x2 (2 elems/op) + sigmoid via tanh identity.
// ---------------------------------------------------------------------------
__global__ __launch_bounds__(256, 2)
void sparsity_main_kernel(const float* __restrict__ chem,
                          const int* __restrict__ mask,
                          const float* __restrict__ b2,
                          const float* __restrict__ W3,
                          const float* __restrict__ b3,
                          float* __restrict__ out) {
    const int i = blockIdx.x;
    const int b = blockIdx.y;
    const int tid = threadIdx.x;            // == row j
    const int lane = tid & 31;
    const int wid = tid >> 5;

    extern __shared__ char sm[];
    const uint32_t smb = smem_u32(sm);
    float* smf = (float*)sm;

    // ---- cooperative smem fills ----
    for (int idx = tid; idx < DH * DH; idx += 256) {       // Wb1 swizzled [o][k]
        int r = idx >> 6, c = idx & 63;
        *(__nv_bfloat16*)(sm + SM_WB1 + SWZ128((uint32_t)(r * 128 + c * 2))) = g_Wb1[idx];
    }
    for (int idx = tid; idx < DQ * DH; idx += 256) {       // Wb2 swizzled [m][o]
        int r = idx >> 6, c = idx & 63;
        *(__nv_bfloat16*)(sm + SM_WB2 + SWZ128((uint32_t)(r * 128 + c * 2))) = g_Wb2[idx];
    }
    if (tid < DH) {
        smf[SM_NI / 4 + tid]  = g_nproj[((size_t)b * NN + i) * DH + tid];
        smf[SM_B1 / 4 + tid]  = g_b1eff[tid];
        smf[SM_W1C / 4 + tid] = g_w1c[tid];
    }
    if (tid < DQ) smf[SM_B2 / 4 + tid] = b2[tid];
    if (tid < HH) smf[SM_B3 / 4 + tid] = b3[tid];
    smf[SM_W3 / 4 + tid] = W3[tid];

    // per-thread row data
    float npj[DH];
    {
        const float4* rp = (const float4*)(g_nproj + ((size_t)b * NN + tid) * DH);
        #pragma unroll
        for (int q = 0; q < 16; ++q) {
            float4 v = rp[q];
            npj[4*q] = v.x; npj[4*q+1] = v.y; npj[4*q+2] = v.z; npj[4*q+3] = v.w;
        }
    }
    float cd = chem[((size_t)b * NN + i) * NN + tid];
    cd = fminf(fmaxf(cd, 0.0f), MAXD);
    smf[SM_CD / 4 + tid] = cd;
    const float msk = (mask[b * NN + i] && mask[b * NN + tid]) ? 1.0f : 0.0f;

    __syncthreads();   // s_ni ready

    // ---- ef = tanh(nproj_i + nproj_j) via bf16x2 MUFU (2 elems/op) ----
    {
        const float* s_ni = smf + SM_NI / 4;
        uint32_t efp[DH / 2];
        #pragma unroll
        for (int p = 0; p < DH / 2; ++p) {
            float e0 = npj[2*p]     + s_ni[2*p];
            float e1 = npj[2*p + 1] + s_ni[2*p + 1];
            uint32_t pk;
            PACK_BF16X2(pk, e0, e1);
            asm("tanh.approx.bf16x2 %0, %0;" : "+r"(pk));
            efp[p] = pk;
        }
        #pragma unroll
        for (int c = 0; c < 8; ++c) {
            uint32_t off = SWZ128((uint32_t)(tid * 128 + c * 16));
            STS128(smb + SM_BUF + off, efp[4*c], efp[4*c+1], efp[4*c+2], efp[4*c+3]);
        }
    }
    __syncthreads();   // ef + weights visible

    // ================= warp-local tensor pipeline =================
    const int m_base = wid * 32;
    const int g   = lane >> 2;
    const int tig = lane & 3;
    const int rA  = m_base + (lane & 15);
    const int chA = (lane >> 4);
    const int rB  = (lane & 7);
    const int chB = (lane >> 3) & 1;

    // ---- layer 1: A-frags from ef ----
    uint32_t a1f[2][4][4];
    #pragma unroll
    for (int mt = 0; mt < 2; ++mt)
        #pragma unroll
        for (int kt = 0; kt < 4; ++kt)
            ldsm_x4(a1f[mt][kt],
                    smb + SM_BUF + SWZ128((uint32_t)((rA + mt * 16) * 128 + (2*kt + chA) * 16)));
    __syncwarp();

    float cdA[2][2];
    #pragma unroll
    for (int mt = 0; mt < 2; ++mt) {
        cdA[mt][0] = smf[SM_CD / 4 + m_base + mt * 16 + g];
        cdA[mt][1] = smf[SM_CD / 4 + m_base + mt * 16 + g + 8];
    }

    #pragma unroll
    for (int nb = 0; nb < 8; ++nb) {
        uint32_t bf[4][2];
        #pragma unroll
        for (int kt = 0; kt < 4; ++kt)
            ldsm_x2(bf[kt],
                    smb + SM_WB1 + SWZ128((uint32_t)((nb * 8 + rB) * 128 + (2*kt + chB) * 16)));
        const int c0 = nb * 8 + 2 * tig;
        const float b1a = smf[SM_B1 / 4 + c0],  b1b = smf[SM_B1 / 4 + c0 + 1];
        const float wca = smf[SM_W1C / 4 + c0], wcb = smf[SM_W1C / 4 + c0 + 1];
        #pragma unroll
        for (int mt = 0; mt < 2; ++mt) {
            float d0 = 0.f, d1 = 0.f, d2 = 0.f, d3 = 0.f;
            #pragma unroll
            for (int kt = 0; kt < 4; ++kt)
                mma16816(d0, d1, d2, d3,
                         a1f[mt][kt][0], a1f[mt][kt][1], a1f[mt][kt][2], a1f[mt][kt][3],
                         bf[kt][0], bf[kt][1]);
            float v00 = fmaxf(d0 + b1a + cdA[mt][0] * wca, 0.f);
            float v01 = fmaxf(d1 + b1b + cdA[mt][0] * wcb, 0.f);
            float v10 = fmaxf(d2 + b1a + cdA[mt][1] * wca, 0.f);
            float v11 = fmaxf(d3 + b1b + cdA[mt][1] * wcb, 0.f);
            uint32_t p0, p1;
            PACK_BF16X2(p0, v00, v01);
            PACK_BF16X2(p1, v10, v11);
            const int row0 = m_base + mt * 16 + g;
            asm volatile("st.shared.b32 [%0], %1;" ::
                "r"(smb + SM_BUF + SWZ128((uint32_t)(row0 * 128 + c0 * 2))), "r"(p0) : "memory");
            asm volatile("st.shared.b32 [%0], %1;" ::
                "r"(smb + SM_BUF + SWZ128((uint32_t)((row0 + 8) * 128 + c0 * 2))), "r"(p1) : "memory");
        }
    }
    __syncwarp();

    // ---- layer 2: A-frags from h1 (same BUF) ----
    uint32_t a2f[2][4][4];
    #pragma unroll
    for (int mt = 0; mt < 2; ++mt)
        #pragma unroll
        for (int kt = 0; kt < 4; ++kt)
            ldsm_x4(a2f[mt][kt],
                    smb + SM_BUF + SWZ128((uint32_t)((rA + mt * 16) * 128 + (2*kt + chA) * 16)));
    __syncwarp();

    #pragma unroll
    for (int nb = 0; nb < 4; ++nb) {
        uint32_t bf[4][2];
        #pragma unroll
        for (int kt = 0; kt < 4; ++kt)
            ldsm_x2(bf[kt],
                    smb + SM_WB2 + SWZ128((uint32_t)((nb * 8 + rB) * 128 + (2*kt + chB) * 16)));
        const int c0 = nb * 8 + 2 * tig;
        const float b2a = smf[SM_B2 / 4 + c0], b2b = smf[SM_B2 / 4 + c0 + 1];
        #pragma unroll
        for (int mt = 0; mt < 2; ++mt) {
            float d0 = 0.f, d1 = 0.f, d2 = 0.f, d3 = 0.f;
            #pragma unroll
            for (int kt = 0; kt < 4; ++kt)
                mma16816(d0, d1, d2, d3,
                         a2f[mt][kt][0], a2f[mt][kt][1], a2f[mt][kt][2], a2f[mt][kt][3],
                         bf[kt][0], bf[kt][1]);
            const int row0 = m_base + mt * 16 + g;
            const int row1 = row0 + 8;
            *(float*)(sm + SM_BUF + row0 * 128 + (((c0    ) + row0) & 31) * 4) = fmaxf(d0 + b2a, 0.f);
            *(float*)(sm + SM_BUF + row0 * 128 + (((c0 + 1) + row0) & 31) * 4) = fmaxf(d1 + b2b, 0.f);
            *(float*)(sm + SM_BUF + row1 * 128 + (((c0    ) + row1) & 31) * 4) = fmaxf(d2 + b2a, 0.f);
            *(float*)(sm + SM_BUF + row1 * 128 + (((c0 + 1) + row1) & 31) * 4) = fmaxf(d3 + b2b, 0.f);
        }
    }
    __syncwarp();

    // ---- layer 3 (scalar fp32); sigmoid via tanh identity; masked store ----
    {
        float h2[DQ];
        #pragma unroll
        for (int m = 0; m < DQ; ++m)
            h2[m] = *(float*)(sm + SM_BUF + tid * 128 + ((m + tid) & 31) * 4);

        const float* s_W3 = smf + SM_W3 / 4;
        const float* s_b3 = smf + SM_B3 / 4;
        float* ob = out + (size_t)b * HH * NN * NN + (size_t)i * NN + tid;
        #pragma unroll
        for (int h = 0; h < HH; ++h) {
            float acc = s_b3[h];
            #pragma unroll
            for (int m = 0; m < DQ; ++m)
                acc = fmaf(s_W3[h * DQ + m], h2[m], acc);
            float t = acc * 0.5f;
            asm("tanh.approx.f32 %0, %0;" : "+f"(t));      // sigmoid(x) = 0.5 + 0.5*tanh(x/2)
            float p = fmaf(t, 0.5f, 0.5f);
            ob[(size_t)h * NN * NN] = p * msk;
        }
    }
}

// ---------------------------------------------------------------------------
extern "C" void kernel_launch(void* const* d_in, const int* in_sizes, int n_in,
                              void* d_out, int out_size) {
    const float* nf     = (const float*)d_in[0];
    const float* chem   = (const float*)d_in[1];
    const int*   mask   = (const int*)d_in[2];     // bool stored as int32
    const float* W_node = (const float*)d_in[3];
    const float* b_node = (const float*)d_in[4];
    const float* W_edge = (const float*)d_in[5];
    const float* b_edge = (const float*)d_in[6];
    const float* W1     = (const float*)d_in[7];
    const float* b1     = (const float*)d_in[8];
    const float* W2     = (const float*)d_in[9];
    const float* b2     = (const float*)d_in[10];
    const float* W3     = (const float*)d_in[11];
    const float* b3     = (const float*)d_in[12];
    float* out = (float*)d_out;

    cudaFuncSetAttribute(sparsity_main_kernel,
                         cudaFuncAttributeMaxDynamicSharedMemorySize, SM_TOTAL);

    prep_kernel<<<DH + DQ + BB * NN, DH>>>(nf, W_node, b_node, W_edge, b_edge, W1, b1, W2);

    dim3 grid(NN, BB);
    sparsity_main_kernel<<<grid, 256, SM_TOTAL>>>(chem, mask, b2, W3, b3, out);
}

// round 9
// speedup vs baseline: 1.0805x; 1.0805x over previous
#include <cuda_runtime.h>
#include <cuda_bf16.h>
#include <cstdint>

#define BB 8
#define NN 256
#define DD 128
#define HH 8
#define DH 64
#define DQ 32
#define MAXD 5.0f

// ---------------- device scratch (no allocation allowed) ----------------
__device__ float         g_nproj[BB * NN * DH];   // [B,N,64] fp32
__device__ __nv_bfloat16 g_Wb1[DH * DH];          // folded layer-1 weight [o][k] bf16
__device__ __nv_bfloat16 g_Wb2[DQ * DH];          // W2 [m][o] bf16
__device__ float         g_b1eff[DH];
__device__ float         g_w1c[DH];               // W1[:,96]/MAXD

// ---------------- helpers ----------------
__device__ __forceinline__ uint32_t smem_u32(const void* p) {
    uint32_t a;
    asm("{ .reg .u64 t; cvta.to.shared.u64 t, %1; cvt.u32.u64 %0, t; }" : "=r"(a) : "l"(p));
    return a;
}
#define SWZ128(off) ((off) ^ (((off) >> 3) & 0x70))

// pack -> bf16x2 {lo=a, hi=b}
#define PACK_BF16X2(res, a, b) \
    asm("cvt.rn.satfinite.bf16x2.f32 %0, %1, %2;" : "=r"(res) : "f"(b), "f"(a))

#define STS128(a, r0, r1, r2, r3) \
    asm volatile("st.shared.v4.b32 [%0], {%1,%2,%3,%4};" :: "r"(a), "r"(r0), "r"(r1), "r"(r2), "r"(r3) : "memory")

__device__ __forceinline__ void ldsm_x4(uint32_t* r, uint32_t addr) {
    asm volatile("ldmatrix.sync.aligned.m8n8.x4.shared.b16 {%0,%1,%2,%3}, [%4];"
                 : "=r"(r[0]), "=r"(r[1]), "=r"(r[2]), "=r"(r[3]) : "r"(addr));
}
__device__ __forceinline__ void ldsm_x2(uint32_t* r, uint32_t addr) {
    asm volatile("ldmatrix.sync.aligned.m8n8.x2.shared.b16 {%0,%1}, [%2];"
                 : "=r"(r[0]), "=r"(r[1]) : "r"(addr));
}
__device__ __forceinline__ void mma16816(float& d0, float& d1, float& d2, float& d3,
                                         uint32_t a0, uint32_t a1, uint32_t a2, uint32_t a3,
                                         uint32_t b0, uint32_t b1) {
    asm volatile("mma.sync.aligned.m16n8k16.row.col.f32.bf16.bf16.f32 "
                 "{%0,%1,%2,%3}, {%4,%5,%6,%7}, {%8,%9}, {%0,%1,%2,%3};"
                 : "+f"(d0), "+f"(d1), "+f"(d2), "+f"(d3)
                 : "r"(a0), "r"(a1), "r"(a2), "r"(a3), "r"(b0), "r"(b1));
}

// ---------------- SMEM layout (dynamic) ----------------
#define SM_BUF   0        // 256 rows x 128B : ef(64c) -> h1(64c) -> h2(32c)  (32768)
#define SM_WB1   32768    // 64 x 128B swizzled                               (8192)
#define SM_WB2   40960    // 32 x 128B swizzled                               (4096)
#define SM_W3B   45056    // 8 rows x 80B (bf16, pitch 80)                    (640)
#define SM_CD    45696    // 256 f                                            (1024)
#define SM_MSK   46720    // 256 f                                            (1024)
#define SM_NI    47744    // 64 f
#define SM_B1    48000    // 64 f
#define SM_W1C   48256    // 64 f
#define SM_B2    48512    // 32 f
#define SM_B3    48640    // 8 f
#define SM_TOTAL 48672

// ---------------------------------------------------------------------------
// merged prep: blocks 0..95 fold weights to bf16; blocks 96.. compute nproj.
// ---------------------------------------------------------------------------
__global__ void prep_kernel(const float* __restrict__ nf,
                            const float* __restrict__ Wn,
                            const float* __restrict__ bn,
                            const float* __restrict__ W_edge,
                            const float* __restrict__ b_edge,
                            const float* __restrict__ W1,
                            const float* __restrict__ b1,
                            const float* __restrict__ W2) {
    const int blk = blockIdx.x;
    const int t = threadIdx.x;   // 64 threads
    if (blk < DH) {
        int o = blk, k = t;
        float acc = W1[o * 97 + k];
        #pragma unroll
        for (int m = 0; m < DQ; ++m)
            acc = fmaf(W1[o * 97 + 64 + m], W_edge[m * DD + k], acc);
        g_Wb1[o * DH + k] = __float2bfloat16_rn(acc);
        if (k == 0) {
            float bb = b1[o];
            #pragma unroll
            for (int m = 0; m < DQ; ++m)
                bb = fmaf(W1[o * 97 + 64 + m], b_edge[m], bb);
            g_b1eff[o] = bb;
            g_w1c[o] = W1[o * 97 + 96] * (1.0f / MAXD);
        }
    } else if (blk < DH + DQ) {
        int m = blk - DH;
        g_Wb2[m * DH + t] = __float2bfloat16_rn(W2[m * DH + t]);
    } else {
        int row = blk - (DH + DQ);
        __shared__ float sx[DD];
        const float* x = nf + (size_t)row * DD;
        sx[t] = x[t];
        sx[t + 64] = x[t + 64];
        __syncthreads();
        const float* w = Wn + t * DD;
        float a0 = 0.f, a1 = 0.f, a2 = 0.f, a3 = 0.f;
        #pragma unroll
        for (int k = 0; k < DD; k += 4) {
            a0 = fmaf(w[k + 0], sx[k + 0], a0);
            a1 = fmaf(w[k + 1], sx[k + 1], a1);
            a2 = fmaf(w[k + 2], sx[k + 2], a2);
            a3 = fmaf(w[k + 3], sx[k + 3], a3);
        }
        g_nproj[row * DH + t] = (a0 + a1) + (a2 + a3) + bn[t];
    }
}

// ---------------------------------------------------------------------------
// Main: CTA per (b,i). All 3 layers on mma.sync bf16.
// ---------------------------------------------------------------------------
__global__ __launch_bounds__(256, 2)
void sparsity_main_kernel(const float* __restrict__ chem,
                          const int* __restrict__ mask,
                          const float* __restrict__ b2,
                          const float* __restrict__ W3,
                          const float* __restrict__ b3,
                          float* __restrict__ out) {
    const int i = blockIdx.x;
    const int b = blockIdx.y;
    const int tid = threadIdx.x;            // == row j
    const int lane = tid & 31;
    const int wid = tid >> 5;

    extern __shared__ char sm[];
    const uint32_t smb = smem_u32(sm);
    float* smf = (float*)sm;

    // ---- cooperative smem fills ----
    for (int idx = tid; idx < DH * DH; idx += 256) {       // Wb1 swizzled [o][k]
        int r = idx >> 6, c = idx & 63;
        *(__nv_bfloat16*)(sm + SM_WB1 + SWZ128((uint32_t)(r * 128 + c * 2))) = g_Wb1[idx];
    }
    for (int idx = tid; idx < DQ * DH; idx += 256) {       // Wb2 swizzled [m][o]
        int r = idx >> 6, c = idx & 63;
        *(__nv_bfloat16*)(sm + SM_WB2 + SWZ128((uint32_t)(r * 128 + c * 2))) = g_Wb2[idx];
    }
    // W3 -> bf16 tile [h][k], pitch 80B
    {
        int h = tid >> 5, k = tid & 31;
        *(__nv_bfloat16*)(sm + SM_W3B + h * 80 + k * 2) = __float2bfloat16_rn(W3[tid]);
    }
    if (tid < DH) {
        smf[SM_NI / 4 + tid]  = g_nproj[((size_t)b * NN + i) * DH + tid];
        smf[SM_B1 / 4 + tid]  = g_b1eff[tid];
        smf[SM_W1C / 4 + tid] = g_w1c[tid];
    }
    if (tid < DQ) smf[SM_B2 / 4 + tid] = b2[tid];
    if (tid < HH) smf[SM_B3 / 4 + tid] = b3[tid];

    // per-thread row data
    float npj[DH];
    {
        const float4* rp = (const float4*)(g_nproj + ((size_t)b * NN + tid) * DH);
        #pragma unroll
        for (int q = 0; q < 16; ++q) {
            float4 v = rp[q];
            npj[4*q] = v.x; npj[4*q+1] = v.y; npj[4*q+2] = v.z; npj[4*q+3] = v.w;
        }
    }
    float cd = chem[((size_t)b * NN + i) * NN + tid];
    cd = fminf(fmaxf(cd, 0.0f), MAXD);
    smf[SM_CD / 4 + tid] = cd;
    smf[SM_MSK / 4 + tid] = (mask[b * NN + i] && mask[b * NN + tid]) ? 1.0f : 0.0f;

    __syncthreads();   // s_ni + weights ready

    // ---- ef = tanh(nproj_i + nproj_j) via bf16x2 MUFU -> swizzled BUF ----
    {
        const float* s_ni = smf + SM_NI / 4;
        uint32_t efp[DH / 2];
        #pragma unroll
        for (int p = 0; p < DH / 2; ++p) {
            float e0 = npj[2*p]     + s_ni[2*p];
            float e1 = npj[2*p + 1] + s_ni[2*p + 1];
            uint32_t pk;
            PACK_BF16X2(pk, e0, e1);
            asm("tanh.approx.bf16x2 %0, %0;" : "+r"(pk));
            efp[p] = pk;
        }
        #pragma unroll
        for (int c = 0; c < 8; ++c) {
            uint32_t off = SWZ128((uint32_t)(tid * 128 + c * 16));
            STS128(smb + SM_BUF + off, efp[4*c], efp[4*c+1], efp[4*c+2], efp[4*c+3]);
        }
    }
    __syncwarp();   // BUF rows are warp-local; warp-level ordering suffices

    // ================= warp-local tensor pipeline =================
    const int m_base = wid * 32;
    const int g    = lane >> 2;
    const int tig  = lane & 3;
    const int rA   = m_base + (lane & 15);
    const int chA  = (lane >> 4);
    const int rB2  = (lane & 7);
    const int nsel = (lane >> 4);            // x4 B-load: tile-pair select
    const int chB  = (lane >> 3) & 1;

    // ---- layer 1: A-frags from ef ----
    uint32_t a1f[2][4][4];
    #pragma unroll
    for (int mt = 0; mt < 2; ++mt)
        #pragma unroll
        for (int kt = 0; kt < 4; ++kt)
            ldsm_x4(a1f[mt][kt],
                    smb + SM_BUF + SWZ128((uint32_t)((rA + mt * 16) * 128 + (2*kt + chA) * 16)));
    __syncwarp();

    float cdA[2][2];
    #pragma unroll
    for (int mt = 0; mt < 2; ++mt) {
        cdA[mt][0] = smf[SM_CD / 4 + m_base + mt * 16 + g];
        cdA[mt][1] = smf[SM_CD / 4 + m_base + mt * 16 + g + 8];
    }

    #pragma unroll
    for (int nbp = 0; nbp < 4; ++nbp) {      // pairs of 8-col blocks
        uint32_t bf[4][4];
        #pragma unroll
        for (int kt = 0; kt < 4; ++kt)
            ldsm_x4(bf[kt],
                    smb + SM_WB1 + SWZ128((uint32_t)(((2*nbp + nsel) * 8 + rB2) * 128 + (2*kt + chB) * 16)));
        #pragma unroll
        for (int half = 0; half < 2; ++half) {
            const int nb = 2 * nbp + half;
            const int c0 = nb * 8 + 2 * tig;
            const float b1a = smf[SM_B1 / 4 + c0],  b1b = smf[SM_B1 / 4 + c0 + 1];
            const float wca = smf[SM_W1C / 4 + c0], wcb = smf[SM_W1C / 4 + c0 + 1];
            #pragma unroll
            for (int mt = 0; mt < 2; ++mt) {
                float d0 = 0.f, d1 = 0.f, d2 = 0.f, d3 = 0.f;
                #pragma unroll
                for (int kt = 0; kt < 4; ++kt)
                    mma16816(d0, d1, d2, d3,
                             a1f[mt][kt][0], a1f[mt][kt][1], a1f[mt][kt][2], a1f[mt][kt][3],
                             bf[kt][2*half], bf[kt][2*half + 1]);
                float v00 = fmaxf(d0 + b1a + cdA[mt][0] * wca, 0.f);
                float v01 = fmaxf(d1 + b1b + cdA[mt][0] * wcb, 0.f);
                float v10 = fmaxf(d2 + b1a + cdA[mt][1] * wca, 0.f);
                float v11 = fmaxf(d3 + b1b + cdA[mt][1] * wcb, 0.f);
                uint32_t p0, p1;
                PACK_BF16X2(p0, v00, v01);
                PACK_BF16X2(p1, v10, v11);
                const int row0 = m_base + mt * 16 + g;
                asm volatile("st.shared.b32 [%0], %1;" ::
                    "r"(smb + SM_BUF + SWZ128((uint32_t)(row0 * 128 + c0 * 2))), "r"(p0) : "memory");
                asm volatile("st.shared.b32 [%0], %1;" ::
                    "r"(smb + SM_BUF + SWZ128((uint32_t)((row0 + 8) * 128 + c0 * 2))), "r"(p1) : "memory");
            }
        }
    }
    __syncwarp();

    // ---- layer 2: A-frags from h1 (same BUF), h2 -> bf16 cols 0..31 ----
    uint32_t a2f[2][4][4];
    #pragma unroll
    for (int mt = 0; mt < 2; ++mt)
        #pragma unroll
        for (int kt = 0; kt < 4; ++kt)
            ldsm_x4(a2f[mt][kt],
                    smb + SM_BUF + SWZ128((uint32_t)((rA + mt * 16) * 128 + (2*kt + chA) * 16)));
    __syncwarp();

    #pragma unroll
    for (int nbp = 0; nbp < 2; ++nbp) {
        uint32_t bf[4][4];
        #pragma unroll
        for (int kt = 0; kt < 4; ++kt)
            ldsm_x4(bf[kt],
                    smb + SM_WB2 + SWZ128((uint32_t)(((2*nbp + nsel) * 8 + rB2) * 128 + (2*kt + chB) * 16)));
        #pragma unroll
        for (int half = 0; half < 2; ++half) {
            const int nb = 2 * nbp + half;
            const int c0 = nb * 8 + 2 * tig;
            const float b2a = smf[SM_B2 / 4 + c0], b2b = smf[SM_B2 / 4 + c0 + 1];
            #pragma unroll
            for (int mt = 0; mt < 2; ++mt) {
                float d0 = 0.f, d1 = 0.f, d2 = 0.f, d3 = 0.f;
                #pragma unroll
                for (int kt = 0; kt < 4; ++kt)
                    mma16816(d0, d1, d2, d3,
                             a2f[mt][kt][0], a2f[mt][kt][1], a2f[mt][kt][2], a2f[mt][kt][3],
                             bf[kt][2*half], bf[kt][2*half + 1]);
                float v00 = fmaxf(d0 + b2a, 0.f);
                float v01 = fmaxf(d1 + b2b, 0.f);
                float v10 = fmaxf(d2 + b2a, 0.f);
                float v11 = fmaxf(d3 + b2b, 0.f);
                uint32_t p0, p1;
                PACK_BF16X2(p0, v00, v01);
                PACK_BF16X2(p1, v10, v11);
                const int row0 = m_base + mt * 16 + g;
                asm volatile("st.shared.b32 [%0], %1;" ::
                    "r"(smb + SM_BUF + SWZ128((uint32_t)(row0 * 128 + c0 * 2))), "r"(p0) : "memory");
                asm volatile("st.shared.b32 [%0], %1;" ::
                    "r"(smb + SM_BUF + SWZ128((uint32_t)((row0 + 8) * 128 + c0 * 2))), "r"(p1) : "memory");
            }
        }
    }
    __syncwarp();

    // ---- layer 3 MMA: logits[j, h] = h2 @ W3^T; sigmoid; direct masked store ----
    {
        uint32_t a3f[2][2][4];
        #pragma unroll
        for (int mt = 0; mt < 2; ++mt)
            #pragma unroll
            for (int kt = 0; kt < 2; ++kt)
                ldsm_x4(a3f[mt][kt],
                        smb + SM_BUF + SWZ128((uint32_t)((rA + mt * 16) * 128 + (2*kt + chA) * 16)));
        uint32_t b3f[2][2];
        #pragma unroll
        for (int kt = 0; kt < 2; ++kt)
            ldsm_x2(b3f[kt], smb + SM_W3B + (uint32_t)(rB2 * 80 + (2*kt + chB) * 16));

        const int c0 = 2 * tig;                 // h indices c0, c0+1
        const float b3a = smf[SM_B3 / 4 + c0], b3b = smf[SM_B3 / 4 + c0 + 1];
        float* outb = out + (size_t)b * HH * NN * NN + (size_t)i * NN;

        #pragma unroll
        for (int mt = 0; mt < 2; ++mt) {
            float d0 = 0.f, d1 = 0.f, d2 = 0.f, d3 = 0.f;
            #pragma unroll
            for (int kt = 0; kt < 2; ++kt)
                mma16816(d0, d1, d2, d3,
                         a3f[mt][kt][0], a3f[mt][kt][1], a3f[mt][kt][2], a3f[mt][kt][3],
                         b3f[kt][0], b3f[kt][1]);
            const int row0 = m_base + mt * 16 + g;
            const int row1 = row0 + 8;
            const float m0 = smf[SM_MSK / 4 + row0];
            const float m1 = smf[SM_MSK / 4 + row1];
            float t0 = (d0 + b3a) * 0.5f, t1 = (d1 + b3b) * 0.5f;
            float t2 = (d2 + b3a) * 0.5f, t3 = (d3 + b3b) * 0.5f;
            asm("tanh.approx.f32 %0, %0;" : "+f"(t0));
            asm("tanh.approx.f32 %0, %0;" : "+f"(t1));
            asm("tanh.approx.f32 %0, %0;" : "+f"(t2));
            asm("tanh.approx.f32 %0, %0;" : "+f"(t3));
            outb[(size_t)(c0    ) * NN * NN + row0] = fmaf(t0, 0.5f, 0.5f) * m0;
            outb[(size_t)(c0 + 1) * NN * NN + row0] = fmaf(t1, 0.5f, 0.5f) * m0;
            outb[(size_t)(c0    ) * NN * NN + row1] = fmaf(t2, 0.5f, 0.5f) * m1;
            outb[(size_t)(c0 + 1) * NN * NN + row1] = fmaf(t3, 0.5f, 0.5f) * m1;
        }
    }
}

// ---------------------------------------------------------------------------
extern "C" void kernel_launch(void* const* d_in, const int* in_sizes, int n_in,
                              void* d_out, int out_size) {
    const float* nf     = (const float*)d_in[0];
    const float* chem   = (const float*)d_in[1];
    const int*   mask   = (const int*)d_in[2];     // bool stored as int32
    const float* W_node = (const float*)d_in[3];
    const float* b_node = (const float*)d_in[4];
    const float* W_edge = (const float*)d_in[5];
    const float* b_edge = (const float*)d_in[6];
    const float* W1     = (const float*)d_in[7];
    const float* b1     = (const float*)d_in[8];
    const float* W2     = (const float*)d_in[9];
    const float* b2     = (const float*)d_in[10];
    const float* W3     = (const float*)d_in[11];
    const float* b3     = (const float*)d_in[12];
    float* out = (float*)d_out;

    cudaFuncSetAttribute(sparsity_main_kernel,
                         cudaFuncAttributeMaxDynamicSharedMemorySize, SM_TOTAL);

    prep_kernel<<<DH + DQ + BB * NN, DH>>>(nf, W_node, b_node, W_edge, b_edge, W1, b1, W2);

    dim3 grid(NN, BB);
    sparsity_main_kernel<<<grid, 256, SM_TOTAL>>>(chem, mask, b2, W3, b3, out);
}

// round 10
// speedup vs baseline: 1.9054x; 1.7634x over previous
#include <cuda_runtime.h>
#include <cuda_bf16.h>
#include <cstdint>

#define BB 8
#define NN 256
#define DD 128
#define HH 8
#define DH 64
#define DQ 32
#define MAXD 5.0f

// ---------------- device scratch (no allocation allowed) ----------------
__device__ float         g_nproj[BB * NN * DH];   // [B,N,64] fp32
__device__ float         g_WnT[DD * DH];          // W_node transposed [k][o]
__device__ __nv_bfloat16 g_Wb1[DH * DH];          // folded layer-1 weight [o][k] bf16
__device__ __nv_bfloat16 g_Wb2[DQ * DH];          // W2 [m][o] bf16
__device__ float         g_b1eff[DH];
__device__ float         g_w1c[DH];               // W1[:,96]/MAXD

// ---------------- helpers ----------------
__device__ __forceinline__ uint32_t smem_u32(const void* p) {
    uint32_t a;
    asm("{ .reg .u64 t; cvta.to.shared.u64 t, %1; cvt.u32.u64 %0, t; }" : "=r"(a) : "l"(p));
    return a;
}
#define SWZ128(off) ((off) ^ (((off) >> 3) & 0x70))

// pack -> bf16x2 {lo=a, hi=b}
#define PACK_BF16X2(res, a, b) \
    asm("cvt.rn.satfinite.bf16x2.f32 %0, %1, %2;" : "=r"(res) : "f"(b), "f"(a))

#define STS128(a, r0, r1, r2, r3) \
    asm volatile("st.shared.v4.b32 [%0], {%1,%2,%3,%4};" :: "r"(a), "r"(r0), "r"(r1), "r"(r2), "r"(r3) : "memory")

__device__ __forceinline__ void ldsm_x4(uint32_t* r, uint32_t addr) {
    asm volatile("ldmatrix.sync.aligned.m8n8.x4.shared.b16 {%0,%1,%2,%3}, [%4];"
                 : "=r"(r[0]), "=r"(r[1]), "=r"(r[2]), "=r"(r[3]) : "r"(addr));
}
__device__ __forceinline__ void ldsm_x2(uint32_t* r, uint32_t addr) {
    asm volatile("ldmatrix.sync.aligned.m8n8.x2.shared.b16 {%0,%1}, [%2];"
                 : "=r"(r[0]), "=r"(r[1]) : "r"(addr));
}
__device__ __forceinline__ void mma16816(float& d0, float& d1, float& d2, float& d3,
                                         uint32_t a0, uint32_t a1, uint32_t a2, uint32_t a3,
                                         uint32_t b0, uint32_t b1) {
    asm volatile("mma.sync.aligned.m16n8k16.row.col.f32.bf16.bf16.f32 "
                 "{%0,%1,%2,%3}, {%4,%5,%6,%7}, {%8,%9}, {%0,%1,%2,%3};"
                 : "+f"(d0), "+f"(d1), "+f"(d2), "+f"(d3)
                 : "r"(a0), "r"(a1), "r"(a2), "r"(a3), "r"(b0), "r"(b1));
}

// ---------------- SMEM layout (dynamic) ----------------
#define SM_BUF   0        // 256 rows x 128B : ef (bf16, swizzled)            (32768)
#define SM_WB1   32768    // 64 x 128B swizzled                               (8192)
#define SM_WB2   40960    // 32 x 128B swizzled                               (4096)
#define SM_W3B   45056    // 8 rows x 80B (bf16, pitch 80)                    (640)
#define SM_CD    45696    // 256 f                                            (1024)
#define SM_MSK   46720    // 256 f                                            (1024)
#define SM_NI    47744    // 64 f
#define SM_B1    48000    // 64 f
#define SM_W1C   48256    // 64 f
#define SM_B2    48512    // 32 f
#define SM_B3    48640    // 8 f
#define SM_TOTAL 48672

// ---------------------------------------------------------------------------
// prep1: weight folding to bf16 + W_node transpose. grid 224 x 64 threads.
// ---------------------------------------------------------------------------
__global__ void prep1_kernel(const float* __restrict__ Wn,
                             const float* __restrict__ W_edge,
                             const float* __restrict__ b_edge,
                             const float* __restrict__ W1,
                             const float* __restrict__ b1,
                             const float* __restrict__ W2) {
    const int blk = blockIdx.x;
    const int t = threadIdx.x;   // 64 threads
    if (blk < DH) {
        int o = blk, k = t;
        float acc = W1[o * 97 + k];
        #pragma unroll
        for (int m = 0; m < DQ; ++m)
            acc = fmaf(W1[o * 97 + 64 + m], W_edge[m * DD + k], acc);
        g_Wb1[o * DH + k] = __float2bfloat16_rn(acc);
        if (k == 0) {
            float bb = b1[o];
            #pragma unroll
            for (int m = 0; m < DQ; ++m)
                bb = fmaf(W1[o * 97 + 64 + m], b_edge[m], bb);
            g_b1eff[o] = bb;
            g_w1c[o] = W1[o * 97 + 96] * (1.0f / MAXD);
        }
    } else if (blk < DH + DQ) {
        int m = blk - DH;
        g_Wb2[m * DH + t] = __float2bfloat16_rn(W2[m * DH + t]);
    } else {
        int k = blk - (DH + DQ);          // 0..127
        g_WnT[k * DH + t] = Wn[t * DD + k];
    }
}

// ---------------------------------------------------------------------------
// prep2: nproj[row][o] = x[row] . WnT[:,o] + bn[o]  (coalesced WnT reads)
// ---------------------------------------------------------------------------
__global__ void prep2_kernel(const float* __restrict__ nf,
                             const float* __restrict__ bn) {
    const int row = blockIdx.x;
    const int o = threadIdx.x;            // 64 threads
    __shared__ float sx[DD];
    const float* x = nf + (size_t)row * DD;
    sx[o] = x[o];
    sx[o + 64] = x[o + 64];
    __syncthreads();
    float a0 = 0.f, a1 = 0.f, a2 = 0.f, a3 = 0.f;
    #pragma unroll
    for (int k = 0; k < DD; k += 4) {
        a0 = fmaf(g_WnT[(k + 0) * DH + o], sx[k + 0], a0);
        a1 = fmaf(g_WnT[(k + 1) * DH + o], sx[k + 1], a1);
        a2 = fmaf(g_WnT[(k + 2) * DH + o], sx[k + 2], a2);
        a3 = fmaf(g_WnT[(k + 3) * DH + o], sx[k + 3], a3);
    }
    g_nproj[row * DH + o] = (a0 + a1) + (a2 + a3) + bn[o];
}

// ---------------------------------------------------------------------------
// Main: CTA per (b,i). All 3 layers on mma.sync bf16; D->A fragment chaining
// keeps h1/h2 entirely in registers (no smem round-trips).
// ---------------------------------------------------------------------------
__global__ __launch_bounds__(256, 2)
void sparsity_main_kernel(const float* __restrict__ chem,
                          const int* __restrict__ mask,
                          const float* __restrict__ b2,
                          const float* __restrict__ W3,
                          const float* __restrict__ b3,
                          float* __restrict__ out) {
    const int i = blockIdx.x;
    const int b = blockIdx.y;
    const int tid = threadIdx.x;            // == row j
    const int lane = tid & 31;
    const int wid = tid >> 5;

    extern __shared__ char sm[];
    const uint32_t smb = smem_u32(sm);
    float* smf = (float*)sm;

    // ---- cooperative smem fills ----
    for (int idx = tid; idx < DH * DH; idx += 256) {       // Wb1 swizzled [o][k]
        int r = idx >> 6, c = idx & 63;
        *(__nv_bfloat16*)(sm + SM_WB1 + SWZ128((uint32_t)(r * 128 + c * 2))) = g_Wb1[idx];
    }
    for (int idx = tid; idx < DQ * DH; idx += 256) {       // Wb2 swizzled [m][o]
        int r = idx >> 6, c = idx & 63;
        *(__nv_bfloat16*)(sm + SM_WB2 + SWZ128((uint32_t)(r * 128 + c * 2))) = g_Wb2[idx];
    }
    // W3 -> bf16 tile [h][k], pitch 80B
    {
        int h = tid >> 5, k = tid & 31;
        *(__nv_bfloat16*)(sm + SM_W3B + h * 80 + k * 2) = __float2bfloat16_rn(W3[tid]);
    }
    if (tid < DH) {
        smf[SM_NI / 4 + tid]  = g_nproj[((size_t)b * NN + i) * DH + tid];
        smf[SM_B1 / 4 + tid]  = g_b1eff[tid];
        smf[SM_W1C / 4 + tid] = g_w1c[tid];
    }
    if (tid < DQ) smf[SM_B2 / 4 + tid] = b2[tid];
    if (tid < HH) smf[SM_B3 / 4 + tid] = b3[tid];

    // per-thread row data
    float npj[DH];
    {
        const float4* rp = (const float4*)(g_nproj + ((size_t)b * NN + tid) * DH);
        #pragma unroll
        for (int q = 0; q < 16; ++q) {
            float4 v = rp[q];
            npj[4*q] = v.x; npj[4*q+1] = v.y; npj[4*q+2] = v.z; npj[4*q+3] = v.w;
        }
    }
    float cd = chem[((size_t)b * NN + i) * NN + tid];
    cd = fminf(fmaxf(cd, 0.0f), MAXD);
    smf[SM_CD / 4 + tid] = cd;
    smf[SM_MSK / 4 + tid] = (mask[b * NN + i] && mask[b * NN + tid]) ? 1.0f : 0.0f;

    __syncthreads();   // s_ni + weights ready

    // ---- ef = tanh(nproj_i + nproj_j) via bf16x2 MUFU -> swizzled BUF ----
    {
        const float* s_ni = smf + SM_NI / 4;
        uint32_t efp[DH / 2];
        #pragma unroll
        for (int p = 0; p < DH / 2; ++p) {
            float e0 = npj[2*p]     + s_ni[2*p];
            float e1 = npj[2*p + 1] + s_ni[2*p + 1];
            uint32_t pk;
            PACK_BF16X2(pk, e0, e1);
            asm("tanh.approx.bf16x2 %0, %0;" : "+r"(pk));
            efp[p] = pk;
        }
        #pragma unroll
        for (int c = 0; c < 8; ++c) {
            uint32_t off = SWZ128((uint32_t)(tid * 128 + c * 16));
            STS128(smb + SM_BUF + off, efp[4*c], efp[4*c+1], efp[4*c+2], efp[4*c+3]);
        }
    }
    __syncwarp();   // BUF rows are warp-local; warp-level ordering suffices

    // ================= warp-local tensor pipeline =================
    const int m_base = wid * 32;
    const int g    = lane >> 2;
    const int tig  = lane & 3;
    const int rA   = m_base + (lane & 15);
    const int chA  = (lane >> 4);
    const int rB2  = (lane & 7);
    const int nsel = (lane >> 4);            // x4 B-load: tile-pair select
    const int chB  = (lane >> 3) & 1;

    // ---- layer 1: A-frags from ef (only smem A access in the pipeline) ----
    uint32_t a1f[2][4][4];
    #pragma unroll
    for (int mt = 0; mt < 2; ++mt)
        #pragma unroll
        for (int kt = 0; kt < 4; ++kt)
            ldsm_x4(a1f[mt][kt],
                    smb + SM_BUF + SWZ128((uint32_t)((rA + mt * 16) * 128 + (2*kt + chA) * 16)));

    float cdA[2][2];
    #pragma unroll
    for (int mt = 0; mt < 2; ++mt) {
        cdA[mt][0] = smf[SM_CD / 4 + m_base + mt * 16 + g];
        cdA[mt][1] = smf[SM_CD / 4 + m_base + mt * 16 + g + 8];
    }

    // h1 as layer-2 A-fragments, built directly from layer-1 D-fragments.
    // D-frag (d0,d1 -> row g, cols c0,c0+1; d2,d3 -> row g+8) == A-frag slots:
    //   nb even: pack(d0,d1)=a0, pack(d2,d3)=a1 ; nb odd: a2, a3   (kt = nb>>1)
    uint32_t h1A[2][4][4];
    #pragma unroll
    for (int nbp = 0; nbp < 4; ++nbp) {      // pairs of 8-col blocks
        uint32_t bf[4][4];
        #pragma unroll
        for (int kt = 0; kt < 4; ++kt)
            ldsm_x4(bf[kt],
                    smb + SM_WB1 + SWZ128((uint32_t)(((2*nbp + nsel) * 8 + rB2) * 128 + (2*kt + chB) * 16)));
        #pragma unroll
        for (int half = 0; half < 2; ++half) {
            const int nb = 2 * nbp + half;
            const int c0 = nb * 8 + 2 * tig;
            const float b1a = smf[SM_B1 / 4 + c0],  b1b = smf[SM_B1 / 4 + c0 + 1];
            const float wca = smf[SM_W1C / 4 + c0], wcb = smf[SM_W1C / 4 + c0 + 1];
            #pragma unroll
            for (int mt = 0; mt < 2; ++mt) {
                float d0 = 0.f, d1 = 0.f, d2 = 0.f, d3 = 0.f;
                #pragma unroll
                for (int kt = 0; kt < 4; ++kt)
                    mma16816(d0, d1, d2, d3,
                             a1f[mt][kt][0], a1f[mt][kt][1], a1f[mt][kt][2], a1f[mt][kt][3],
                             bf[kt][2*half], bf[kt][2*half + 1]);
                float v00 = fmaxf(d0 + b1a + cdA[mt][0] * wca, 0.f);
                float v01 = fmaxf(d1 + b1b + cdA[mt][0] * wcb, 0.f);
                float v10 = fmaxf(d2 + b1a + cdA[mt][1] * wca, 0.f);
                float v11 = fmaxf(d3 + b1b + cdA[mt][1] * wcb, 0.f);
                PACK_BF16X2(h1A[mt][nb >> 1][(nb & 1) * 2 + 0], v00, v01);
                PACK_BF16X2(h1A[mt][nb >> 1][(nb & 1) * 2 + 1], v10, v11);
            }
        }
    }

    // ---- layer 2: A from h1A registers; h2 as layer-3 A-fragments ----
    uint32_t h2A[2][2][4];
    #pragma unroll
    for (int nbp = 0; nbp < 2; ++nbp) {
        uint32_t bf[4][4];
        #pragma unroll
        for (int kt = 0; kt < 4; ++kt)
            ldsm_x4(bf[kt],
                    smb + SM_WB2 + SWZ128((uint32_t)(((2*nbp + nsel) * 8 + rB2) * 128 + (2*kt + chB) * 16)));
        #pragma unroll
        for (int half = 0; half < 2; ++half) {
            const int nb = 2 * nbp + half;
            const int c0 = nb * 8 + 2 * tig;
            const float b2a = smf[SM_B2 / 4 + c0], b2b = smf[SM_B2 / 4 + c0 + 1];
            #pragma unroll
            for (int mt = 0; mt < 2; ++mt) {
                float d0 = 0.f, d1 = 0.f, d2 = 0.f, d3 = 0.f;
                #pragma unroll
                for (int kt = 0; kt < 4; ++kt)
                    mma16816(d0, d1, d2, d3,
                             h1A[mt][kt][0], h1A[mt][kt][1], h1A[mt][kt][2], h1A[mt][kt][3],
                             bf[kt][2*half], bf[kt][2*half + 1]);
                float v00 = fmaxf(d0 + b2a, 0.f);
                float v01 = fmaxf(d1 + b2b, 0.f);
                float v10 = fmaxf(d2 + b2a, 0.f);
                float v11 = fmaxf(d3 + b2b, 0.f);
                PACK_BF16X2(h2A[mt][nb >> 1][(nb & 1) * 2 + 0], v00, v01);
                PACK_BF16X2(h2A[mt][nb >> 1][(nb & 1) * 2 + 1], v10, v11);
            }
        }
    }

    // ---- layer 3 MMA: A from h2A registers; sigmoid; direct masked store ----
    {
        uint32_t b3f[2][2];
        #pragma unroll
        for (int kt = 0; kt < 2; ++kt)
            ldsm_x2(b3f[kt], smb + SM_W3B + (uint32_t)(rB2 * 80 + (2*kt + chB) * 16));

        const int c0 = 2 * tig;                 // h indices c0, c0+1
        const float b3a = smf[SM_B3 / 4 + c0], b3b = smf[SM_B3 / 4 + c0 + 1];
        float* outb = out + (size_t)b * HH * NN * NN + (size_t)i * NN;

        #pragma unroll
        for (int mt = 0; mt < 2; ++mt) {
            float d0 = 0.f, d1 = 0.f, d2 = 0.f, d3 = 0.f;
            #pragma unroll
            for (int kt = 0; kt < 2; ++kt)
                mma16816(d0, d1, d2, d3,
                         h2A[mt][kt][0], h2A[mt][kt][1], h2A[mt][kt][2], h2A[mt][kt][3],
                         b3f[kt][0], b3f[kt][1]);
            const int row0 = m_base + mt * 16 + g;
            const int row1 = row0 + 8;
            const float m0 = smf[SM_MSK / 4 + row0];
            const float m1 = smf[SM_MSK / 4 + row1];
            float t0 = (d0 + b3a) * 0.5f, t1 = (d1 + b3b) * 0.5f;
            float t2 = (d2 + b3a) * 0.5f, t3 = (d3 + b3b) * 0.5f;
            asm("tanh.approx.f32 %0, %0;" : "+f"(t0));
            asm("tanh.approx.f32 %0, %0;" : "+f"(t1));
            asm("tanh.approx.f32 %0, %0;" : "+f"(t2));
            asm("tanh.approx.f32 %0, %0;" : "+f"(t3));
            outb[(size_t)(c0    ) * NN * NN + row0] = fmaf(t0, 0.5f, 0.5f) * m0;
            outb[(size_t)(c0 + 1) * NN * NN + row0] = fmaf(t1, 0.5f, 0.5f) * m0;
            outb[(size_t)(c0    ) * NN * NN + row1] = fmaf(t2, 0.5f, 0.5f) * m1;
            outb[(size_t)(c0 + 1) * NN * NN + row1] = fmaf(t3, 0.5f, 0.5f) * m1;
        }
    }
}

// ---------------------------------------------------------------------------
extern "C" void kernel_launch(void* const* d_in, const int* in_sizes, int n_in,
                              void* d_out, int out_size) {
    const float* nf     = (const float*)d_in[0];
    const float* chem   = (const float*)d_in[1];
    const int*   mask   = (const int*)d_in[2];     // bool stored as int32
    const float* W_node = (const float*)d_in[3];
    const float* b_node = (const float*)d_in[4];
    const float* W_edge = (const float*)d_in[5];
    const float* b_edge = (const float*)d_in[6];
    const float* W1     = (const float*)d_in[7];
    const float* b1     = (const float*)d_in[8];
    const float* W2     = (const float*)d_in[9];
    const float* b2     = (const float*)d_in[10];
    const float* W3     = (const float*)d_in[11];
    const float* b3     = (const float*)d_in[12];
    float* out = (float*)d_out;

    cudaFuncSetAttribute(sparsity_main_kernel,
                         cudaFuncAttributeMaxDynamicSharedMemorySize, SM_TOTAL);

    prep1_kernel<<<DH + DQ + DD, DH>>>(W_node, W_edge, b_edge, W1, b1, W2);
    prep2_kernel<<<BB * NN, DH>>>(nf, b_node);

    dim3 grid(NN, BB);
    sparsity_main_kernel<<<grid, 256, SM_TOTAL>>>(chem, mask, b2, W3, b3, out);
}

// round 11
// speedup vs baseline: 2.7480x; 1.4422x over previous
#include <cuda_runtime.h>
#include <cuda_bf16.h>
#include <cstdint>

#define BB 8
#define NN 256
#define DD 128
#define HH 8
#define DH 64
#define DQ 32
#define MAXD 5.0f

// ---------------- device scratch (no allocation allowed) ----------------
__device__ float         g_nproj[BB * NN * DH];   // [B,N,64] row-major (for s_ni col read)
__device__ float         g_nprojT[BB * DH * NN];  // [B,64,N] o-major (coalesced per-thread read)
__device__ float         g_WnT[DD * DH];          // W_node transposed [k][o]
__device__ __nv_bfloat16 g_Wb1[DH * DH];          // folded layer-1 weight [o][k] bf16
__device__ __nv_bfloat16 g_Wb2[DQ * DH];          // W2 [m][o] bf16
__device__ float         g_b1eff[DH];
__device__ float         g_w1c[DH];               // W1[:,96]/MAXD

// ---------------- helpers ----------------
__device__ __forceinline__ uint32_t smem_u32(const void* p) {
    uint32_t a;
    asm("{ .reg .u64 t; cvta.to.shared.u64 t, %1; cvt.u32.u64 %0, t; }" : "=r"(a) : "l"(p));
    return a;
}
#define SWZ128(off) ((off) ^ (((off) >> 3) & 0x70))

// pack -> bf16x2 {lo=a, hi=b}
#define PACK_BF16X2(res, a, b) \
    asm("cvt.rn.satfinite.bf16x2.f32 %0, %1, %2;" : "=r"(res) : "f"(b), "f"(a))

#define STS128(a, r0, r1, r2, r3) \
    asm volatile("st.shared.v4.b32 [%0], {%1,%2,%3,%4};" :: "r"(a), "r"(r0), "r"(r1), "r"(r2), "r"(r3) : "memory")

__device__ __forceinline__ void ldsm_x4(uint32_t* r, uint32_t addr) {
    asm volatile("ldmatrix.sync.aligned.m8n8.x4.shared.b16 {%0,%1,%2,%3}, [%4];"
                 : "=r"(r[0]), "=r"(r[1]), "=r"(r[2]), "=r"(r[3]) : "r"(addr));
}
__device__ __forceinline__ void ldsm_x2(uint32_t* r, uint32_t addr) {
    asm volatile("ldmatrix.sync.aligned.m8n8.x2.shared.b16 {%0,%1}, [%2];"
                 : "=r"(r[0]), "=r"(r[1]) : "r"(addr));
}
__device__ __forceinline__ void mma16816(float& d0, float& d1, float& d2, float& d3,
                                         uint32_t a0, uint32_t a1, uint32_t a2, uint32_t a3,
                                         uint32_t b0, uint32_t b1) {
    asm volatile("mma.sync.aligned.m16n8k16.row.col.f32.bf16.bf16.f32 "
                 "{%0,%1,%2,%3}, {%4,%5,%6,%7}, {%8,%9}, {%0,%1,%2,%3};"
                 : "+f"(d0), "+f"(d1), "+f"(d2), "+f"(d3)
                 : "r"(a0), "r"(a1), "r"(a2), "r"(a3), "r"(b0), "r"(b1));
}

// ---------------- SMEM layout (dynamic) ----------------
#define SM_BUF   0        // 256 rows x 128B : ef (bf16, swizzled)            (32768)
#define SM_WB1   32768    // 64 x 128B swizzled                               (8192)
#define SM_WB2   40960    // 32 x 128B swizzled                               (4096)
#define SM_W3B   45056    // 8 rows x 80B (bf16, pitch 80)                    (640)
#define SM_CD    45696    // 256 f                                            (1024)
#define SM_MSK   46720    // 256 f                                            (1024)
#define SM_NI    47744    // 64 f
#define SM_B1    48000    // 64 f
#define SM_W1C   48256    // 64 f
#define SM_B2    48512    // 32 f
#define SM_B3    48640    // 8 f
#define SM_TOTAL 48672

// ---------------------------------------------------------------------------
// prep1: weight folding to bf16 + W_node transpose. grid 224 x 64 threads.
// ---------------------------------------------------------------------------
__global__ void prep1_kernel(const float* __restrict__ Wn,
                             const float* __restrict__ W_edge,
                             const float* __restrict__ b_edge,
                             const float* __restrict__ W1,
                             const float* __restrict__ b1,
                             const float* __restrict__ W2) {
    const int blk = blockIdx.x;
    const int t = threadIdx.x;   // 64 threads
    if (blk < DH) {
        int o = blk, k = t;
        float acc = W1[o * 97 + k];
        #pragma unroll
        for (int m = 0; m < DQ; ++m)
            acc = fmaf(W1[o * 97 + 64 + m], W_edge[m * DD + k], acc);
        g_Wb1[o * DH + k] = __float2bfloat16_rn(acc);
        if (k == 0) {
            float bb = b1[o];
            #pragma unroll
            for (int m = 0; m < DQ; ++m)
                bb = fmaf(W1[o * 97 + 64 + m], b_edge[m], bb);
            g_b1eff[o] = bb;
            g_w1c[o] = W1[o * 97 + 96] * (1.0f / MAXD);
        }
    } else if (blk < DH + DQ) {
        int m = blk - DH;
        g_Wb2[m * DH + t] = __float2bfloat16_rn(W2[m * DH + t]);
    } else {
        int k = blk - (DH + DQ);          // 0..127
        g_WnT[k * DH + t] = Wn[t * DD + k];
    }
}

// ---------------------------------------------------------------------------
// prep2: nproj[row][o] = x[row] . WnT[:,o] + bn[o]  (coalesced WnT reads)
// Writes row-major AND o-major transposed copies.
// ---------------------------------------------------------------------------
__global__ void prep2_kernel(const float* __restrict__ nf,
                             const float* __restrict__ bn) {
    const int row = blockIdx.x;           // b*256 + n
    const int o = threadIdx.x;            // 64 threads
    __shared__ float sx[DD];
    const float* x = nf + (size_t)row * DD;
    sx[o] = x[o];
    sx[o + 64] = x[o + 64];
    __syncthreads();
    float a0 = 0.f, a1 = 0.f, a2 = 0.f, a3 = 0.f;
    #pragma unroll
    for (int k = 0; k < DD; k += 4) {
        a0 = fmaf(g_WnT[(k + 0) * DH + o], sx[k + 0], a0);
        a1 = fmaf(g_WnT[(k + 1) * DH + o], sx[k + 1], a1);
        a2 = fmaf(g_WnT[(k + 2) * DH + o], sx[k + 2], a2);
        a3 = fmaf(g_WnT[(k + 3) * DH + o], sx[k + 3], a3);
    }
    const float v = (a0 + a1) + (a2 + a3) + bn[o];
    g_nproj[row * DH + o] = v;
    const int b = row >> 8, n = row & 255;
    g_nprojT[((size_t)b * DH + o) * NN + n] = v;
}

// ---------------------------------------------------------------------------
// Main: CTA per (b,i). All 3 layers on mma.sync bf16; D->A fragment chaining
// keeps h1/h2 entirely in registers (no smem round-trips).
// ---------------------------------------------------------------------------
__global__ __launch_bounds__(256, 2)
void sparsity_main_kernel(const float* __restrict__ chem,
                          const int* __restrict__ mask,
                          const float* __restrict__ b2,
                          const float* __restrict__ W3,
                          const float* __restrict__ b3,
                          float* __restrict__ out) {
    const int i = blockIdx.x;
    const int b = blockIdx.y;
    const int tid = threadIdx.x;            // == row j
    const int lane = tid & 31;
    const int wid = tid >> 5;

    extern __shared__ char sm[];
    const uint32_t smb = smem_u32(sm);
    float* smf = (float*)sm;

    // ---- cooperative smem fills ----
    for (int idx = tid; idx < DH * DH; idx += 256) {       // Wb1 swizzled [o][k]
        int r = idx >> 6, c = idx & 63;
        *(__nv_bfloat16*)(sm + SM_WB1 + SWZ128((uint32_t)(r * 128 + c * 2))) = g_Wb1[idx];
    }
    for (int idx = tid; idx < DQ * DH; idx += 256) {       // Wb2 swizzled [m][o]
        int r = idx >> 6, c = idx & 63;
        *(__nv_bfloat16*)(sm + SM_WB2 + SWZ128((uint32_t)(r * 128 + c * 2))) = g_Wb2[idx];
    }
    // W3 -> bf16 tile [h][k], pitch 80B
    {
        int h = tid >> 5, k = tid & 31;
        *(__nv_bfloat16*)(sm + SM_W3B + h * 80 + k * 2) = __float2bfloat16_rn(W3[tid]);
    }
    if (tid < DH) {
        smf[SM_NI / 4 + tid]  = g_nproj[((size_t)b * NN + i) * DH + tid];
        smf[SM_B1 / 4 + tid]  = g_b1eff[tid];
        smf[SM_W1C / 4 + tid] = g_w1c[tid];
    }
    if (tid < DQ) smf[SM_B2 / 4 + tid] = b2[tid];
    if (tid < HH) smf[SM_B3 / 4 + tid] = b3[tid];

    // per-thread row data (coalesced: o-major layout, consecutive tid -> consecutive addr)
    float npj[DH];
    {
        const float* npT = g_nprojT + (size_t)b * DH * NN + tid;
        #pragma unroll
        for (int o = 0; o < DH; ++o)
            npj[o] = npT[(size_t)o * NN];
    }
    float cd = chem[((size_t)b * NN + i) * NN + tid];
    cd = fminf(fmaxf(cd, 0.0f), MAXD);
    smf[SM_CD / 4 + tid] = cd;
    smf[SM_MSK / 4 + tid] = (mask[b * NN + i] && mask[b * NN + tid]) ? 1.0f : 0.0f;

    __syncthreads();   // s_ni + weights ready

    // ---- ef = tanh(nproj_i + nproj_j) via bf16x2 MUFU -> swizzled BUF ----
    {
        const float* s_ni = smf + SM_NI / 4;
        uint32_t efp[DH / 2];
        #pragma unroll
        for (int p = 0; p < DH / 2; ++p) {
            float e0 = npj[2*p]     + s_ni[2*p];
            float e1 = npj[2*p + 1] + s_ni[2*p + 1];
            uint32_t pk;
            PACK_BF16X2(pk, e0, e1);
            asm("tanh.approx.bf16x2 %0, %0;" : "+r"(pk));
            efp[p] = pk;
        }
        #pragma unroll
        for (int c = 0; c < 8; ++c) {
            uint32_t off = SWZ128((uint32_t)(tid * 128 + c * 16));
            STS128(smb + SM_BUF + off, efp[4*c], efp[4*c+1], efp[4*c+2], efp[4*c+3]);
        }
    }
    __syncwarp();   // BUF rows are warp-local; warp-level ordering suffices

    // ================= warp-local tensor pipeline =================
    const int m_base = wid * 32;
    const int g    = lane >> 2;
    const int tig  = lane & 3;
    const int rA   = m_base + (lane & 15);
    const int chA  = (lane >> 4);
    const int rB2  = (lane & 7);
    const int nsel = (lane >> 4);            // x4 B-load: tile-pair select
    const int chB  = (lane >> 3) & 1;

    // ---- layer 1: A-frags from ef (only smem A access in the pipeline) ----
    uint32_t a1f[2][4][4];
    #pragma unroll
    for (int mt = 0; mt < 2; ++mt)
        #pragma unroll
        for (int kt = 0; kt < 4; ++kt)
            ldsm_x4(a1f[mt][kt],
                    smb + SM_BUF + SWZ128((uint32_t)((rA + mt * 16) * 128 + (2*kt + chA) * 16)));

    float cdA[2][2];
    #pragma unroll
    for (int mt = 0; mt < 2; ++mt) {
        cdA[mt][0] = smf[SM_CD / 4 + m_base + mt * 16 + g];
        cdA[mt][1] = smf[SM_CD / 4 + m_base + mt * 16 + g + 8];
    }

    // h1 as layer-2 A-fragments, built directly from layer-1 D-fragments.
    uint32_t h1A[2][4][4];
    #pragma unroll
    for (int nbp = 0; nbp < 4; ++nbp) {      // pairs of 8-col blocks
        uint32_t bf[4][4];
        #pragma unroll
        for (int kt = 0; kt < 4; ++kt)
            ldsm_x4(bf[kt],
                    smb + SM_WB1 + SWZ128((uint32_t)(((2*nbp + nsel) * 8 + rB2) * 128 + (2*kt + chB) * 16)));
        #pragma unroll
        for (int half = 0; half < 2; ++half) {
            const int nb = 2 * nbp + half;
            const int c0 = nb * 8 + 2 * tig;
            const float b1a = smf[SM_B1 / 4 + c0],  b1b = smf[SM_B1 / 4 + c0 + 1];
            const float wca = smf[SM_W1C / 4 + c0], wcb = smf[SM_W1C / 4 + c0 + 1];
            #pragma unroll
            for (int mt = 0; mt < 2; ++mt) {
                float d0 = 0.f, d1 = 0.f, d2 = 0.f, d3 = 0.f;
                #pragma unroll
                for (int kt = 0; kt < 4; ++kt)
                    mma16816(d0, d1, d2, d3,
                             a1f[mt][kt][0], a1f[mt][kt][1], a1f[mt][kt][2], a1f[mt][kt][3],
                             bf[kt][2*half], bf[kt][2*half + 1]);
                float v00 = fmaxf(d0 + b1a + cdA[mt][0] * wca, 0.f);
                float v01 = fmaxf(d1 + b1b + cdA[mt][0] * wcb, 0.f);
                float v10 = fmaxf(d2 + b1a + cdA[mt][1] * wca, 0.f);
                float v11 = fmaxf(d3 + b1b + cdA[mt][1] * wcb, 0.f);
                PACK_BF16X2(h1A[mt][nb >> 1][(nb & 1) * 2 + 0], v00, v01);
                PACK_BF16X2(h1A[mt][nb >> 1][(nb & 1) * 2 + 1], v10, v11);
            }
        }
    }

    // ---- layer 2: A from h1A registers; h2 as layer-3 A-fragments ----
    uint32_t h2A[2][2][4];
    #pragma unroll
    for (int nbp = 0; nbp < 2; ++nbp) {
        uint32_t bf[4][4];
        #pragma unroll
        for (int kt = 0; kt < 4; ++kt)
            ldsm_x4(bf[kt],
                    smb + SM_WB2 + SWZ128((uint32_t)(((2*nbp + nsel) * 8 + rB2) * 128 + (2*kt + chB) * 16)));
        #pragma unroll
        for (int half = 0; half < 2; ++half) {
            const int nb = 2 * nbp + half;
            const int c0 = nb * 8 + 2 * tig;
            const float b2a = smf[SM_B2 / 4 + c0], b2b = smf[SM_B2 / 4 + c0 + 1];
            #pragma unroll
            for (int mt = 0; mt < 2; ++mt) {
                float d0 = 0.f, d1 = 0.f, d2 = 0.f, d3 = 0.f;
                #pragma unroll
                for (int kt = 0; kt < 4; ++kt)
                    mma16816(d0, d1, d2, d3,
                             h1A[mt][kt][0], h1A[mt][kt][1], h1A[mt][kt][2], h1A[mt][kt][3],
                             bf[kt][2*half], bf[kt][2*half + 1]);
                float v00 = fmaxf(d0 + b2a, 0.f);
                float v01 = fmaxf(d1 + b2b, 0.f);
                float v10 = fmaxf(d2 + b2a, 0.f);
                float v11 = fmaxf(d3 + b2b, 0.f);
                PACK_BF16X2(h2A[mt][nb >> 1][(nb & 1) * 2 + 0], v00, v01);
                PACK_BF16X2(h2A[mt][nb >> 1][(nb & 1) * 2 + 1], v10, v11);
            }
        }
    }

    // ---- layer 3 MMA: A from h2A registers; sigmoid; direct masked store ----
    {
        uint32_t b3f[2][2];
        #pragma unroll
        for (int kt = 0; kt < 2; ++kt)
            ldsm_x2(b3f[kt], smb + SM_W3B + (uint32_t)(rB2 * 80 + (2*kt + chB) * 16));

        const int c0 = 2 * tig;                 // h indices c0, c0+1
        const float b3a = smf[SM_B3 / 4 + c0], b3b = smf[SM_B3 / 4 + c0 + 1];
        float* outb = out + (size_t)b * HH * NN * NN + (size_t)i * NN;

        #pragma unroll
        for (int mt = 0; mt < 2; ++mt) {
            float d0 = 0.f, d1 = 0.f, d2 = 0.f, d3 = 0.f;
            #pragma unroll
            for (int kt = 0; kt < 2; ++kt)
                mma16816(d0, d1, d2, d3,
                         h2A[mt][kt][0], h2A[mt][kt][1], h2A[mt][kt][2], h2A[mt][kt][3],
                         b3f[kt][0], b3f[kt][1]);
            const int row0 = m_base + mt * 16 + g;
            const int row1 = row0 + 8;
            const float m0 = smf[SM_MSK / 4 + row0];
            const float m1 = smf[SM_MSK / 4 + row1];
            float t0 = (d0 + b3a) * 0.5f, t1 = (d1 + b3b) * 0.5f;
            float t2 = (d2 + b3a) * 0.5f, t3 = (d3 + b3b) * 0.5f;
            asm("tanh.approx.f32 %0, %0;" : "+f"(t0));
            asm("tanh.approx.f32 %0, %0;" : "+f"(t1));
            asm("tanh.approx.f32 %0, %0;" : "+f"(t2));
            asm("tanh.approx.f32 %0, %0;" : "+f"(t3));
            outb[(size_t)(c0    ) * NN * NN + row0] = fmaf(t0, 0.5f, 0.5f) * m0;
            outb[(size_t)(c0 + 1) * NN * NN + row0] = fmaf(t1, 0.5f, 0.5f) * m0;
            outb[(size_t)(c0    ) * NN * NN + row1] = fmaf(t2, 0.5f, 0.5f) * m1;
            outb[(size_t)(c0 + 1) * NN * NN + row1] = fmaf(t3, 0.5f, 0.5f) * m1;
        }
    }
}

// ---------------------------------------------------------------------------
extern "C" void kernel_launch(void* const* d_in, const int* in_sizes, int n_in,
                              void* d_out, int out_size) {
    const float* nf     = (const float*)d_in[0];
    const float* chem   = (const float*)d_in[1];
    const int*   mask   = (const int*)d_in[2];     // bool stored as int32
    const float* W_node = (const float*)d_in[3];
    const float* b_node = (const float*)d_in[4];
    const float* W_edge = (const float*)d_in[5];
    const float* b_edge = (const float*)d_in[6];
    const float* W1     = (const float*)d_in[7];
    const float* b1     = (const float*)d_in[8];
    const float* W2     = (const float*)d_in[9];
    const float* b2     = (const float*)d_in[10];
    const float* W3     = (const float*)d_in[11];
    const float* b3     = (const float*)d_in[12];
    float* out = (float*)d_out;

    cudaFuncSetAttribute(sparsity_main_kernel,
                         cudaFuncAttributeMaxDynamicSharedMemorySize, SM_TOTAL);

    prep1_kernel<<<DH + DQ + DD, DH>>>(W_node, W_edge, b_edge, W1, b1, W2);
    prep2_kernel<<<BB * NN, DH>>>(nf, b_node);

    dim3 grid(NN, BB);
    sparsity_main_kernel<<<grid, 256, SM_TOTAL>>>(chem, mask, b2, W3, b3, out);
}